// round 1
// baseline (speedup 1.0000x reference)
#include <cuda_runtime.h>
#include <stdint.h>

#define NV       64000
#define C        64
#define NY       496
#define NX       432
#define B        4
#define NPIX     (NY * NX)          // 214272
#define NPILLARS (B * NPIX)         // 857088

// Scratch: pillar -> voxel index map (-1 = empty). __device__ global (no alloc).
__device__ int g_idx[NPILLARS];

// ---------------------------------------------------------------------------
// Kernel 1: fill index map with -1 (vectorized, NPILLARS divisible by 4)
// ---------------------------------------------------------------------------
__global__ void fill_idx_kernel() {
    int i = blockIdx.x * blockDim.x + threadIdx.x;
    if (i < NPILLARS / 4) {
        reinterpret_cast<int4*>(g_idx)[i] = make_int4(-1, -1, -1, -1);
    }
}

// ---------------------------------------------------------------------------
// Kernel 2: scatter voxel indices. atomicMax => highest voxel index wins on
// duplicate coords, matching JAX's sequential .at[].set (last write wins).
// ---------------------------------------------------------------------------
__global__ void scatter_idx_kernel(const int* __restrict__ coors) {
    int v = blockIdx.x * blockDim.x + threadIdx.x;
    if (v < NV) {
        const int4 c = reinterpret_cast<const int4*>(coors)[v];  // [b, z, y, x]
        int flat = c.x * NPIX + c.z * NX + c.w;
        atomicMax(&g_idx[flat], v);
    }
}

// ---------------------------------------------------------------------------
// Kernel 3: dense gather. One thread per pillar slot (y,x) within batch b
// (blockIdx.y = b). Reads idx once, writes all 64 channels coalesced
// (consecutive threads -> consecutive x -> contiguous 4B stores per channel).
// vf reads are 16x float4 = 256B sequential per occupied voxel.
// ---------------------------------------------------------------------------
__global__ void gather_kernel(const float4* __restrict__ vf,
                              float* __restrict__ out) {
    int pos = blockIdx.x * blockDim.x + threadIdx.x;
    if (pos >= NPIX) return;
    int b = blockIdx.y;

    int idx = g_idx[b * NPIX + pos];
    float* outp = out + (size_t)b * C * NPIX + pos;

    if (idx >= 0) {
        const float4* v4 = vf + (size_t)idx * (C / 4);
#pragma unroll
        for (int i = 0; i < C / 4; i++) {
            float4 f = __ldg(&v4[i]);
            outp[(size_t)(4 * i + 0) * NPIX] = f.x;
            outp[(size_t)(4 * i + 1) * NPIX] = f.y;
            outp[(size_t)(4 * i + 2) * NPIX] = f.z;
            outp[(size_t)(4 * i + 3) * NPIX] = f.w;
        }
    } else {
#pragma unroll
        for (int c = 0; c < C; c++) {
            outp[(size_t)c * NPIX] = 0.0f;
        }
    }
}

// ---------------------------------------------------------------------------
extern "C" void kernel_launch(void* const* d_in, const int* in_sizes, int n_in,
                              void* d_out, int out_size) {
    const float* voxel_features = (const float*)d_in[0];
    const int*   coors          = (const int*)d_in[1];
    // d_in[2] = batch_size (compile-time constant B=4 here)
    float* out = (float*)d_out;

    {
        int n = NPILLARS / 4;
        fill_idx_kernel<<<(n + 255) / 256, 256>>>();
    }
    scatter_idx_kernel<<<(NV + 255) / 256, 256>>>(coors);
    {
        dim3 grid((NPIX + 255) / 256, B);
        gather_kernel<<<grid, 256>>>((const float4*)voxel_features, out);
    }
}